// round 12
// baseline (speedup 1.0000x reference)
#include <cuda_runtime.h>
#include <cuda_bf16.h>

#define N_NODES 100000
#define N_EDGES 1600000
#define IN_CH 128
#define HID_CH 64
#define OUT_CH 64

#define SCAN_CHUNK 1024
#define SCAN_BLOCKS ((N_NODES + SCAN_CHUNK - 1) / SCAN_CHUNK)   // 98

// ---------------- scratch (device globals; device-code access ONLY) ---------
__device__ int   g_idx64;
__device__ int   g_row[N_EDGES];
__device__ int   g_col[N_EDGES];
__device__ int   g_csr[N_EDGES];            // source indices grouped by dst
__device__ int   g_deg[N_NODES];            // 1 + in-degree (self-loop incl.)
__device__ int   g_start[N_NODES + 1];      // CSR offsets (edges only)
__device__ int   g_cur[N_NODES];            // scatter cursors
__device__ int   g_bsum[SCAN_BLOCKS];
__device__ float g_dinv[N_NODES];
__device__ float g_hs [N_NODES * HID_CH];   // dinv-scaled features (msg source)
__device__ float g_h2 [N_NODES * HID_CH];   // layer-2 msg source

// ---------------- probe (block 0) + deg init (all blocks), one launch --------
__global__ void probe_init_kernel(const void* ei) {
    int i = blockIdx.x * blockDim.x + threadIdx.x;
    if (i < N_NODES) g_deg[i] = 1;   // self-loop
    if (blockIdx.x == 0) {
        __shared__ int ok;
        if (threadIdx.x == 0) ok = 1;
        __syncthreads();
        const long long* p = (const long long*)ei;
        for (int j = threadIdx.x; j < 1024; j += blockDim.x) {
            long long v = p[j];
            if (v < 0 || v >= N_NODES) ok = 0;
        }
        __syncthreads();
        if (threadIdx.x == 0) g_idx64 = ok;
    }
}

// fused convert + clamp + degree histogram; 2 edges per thread (vector loads)
__global__ void convert_count_kernel(const void* ei) {
    int t = blockIdx.x * blockDim.x + threadIdx.x;
    int e = t * 2;
    if (e >= N_EDGES) return;
    long long r0, r1, c0, c1;
    if (g_idx64) {
        const longlong2* p = (const longlong2*)ei;
        longlong2 rr = p[t];
        longlong2 cc = p[(N_EDGES / 2) + t];
        r0 = rr.x; r1 = rr.y; c0 = cc.x; c1 = cc.y;
    } else {
        const int2* p = (const int2*)ei;
        int2 rr = p[t];
        int2 cc = p[(N_EDGES / 2) + t];
        r0 = rr.x; r1 = rr.y; c0 = cc.x; c1 = cc.y;
    }
    if (r0 < 0) r0 = 0; if (r0 >= N_NODES) r0 = N_NODES - 1;
    if (r1 < 0) r1 = 0; if (r1 >= N_NODES) r1 = N_NODES - 1;
    if (c0 < 0) c0 = 0; if (c0 >= N_NODES) c0 = N_NODES - 1;
    if (c1 < 0) c1 = 0; if (c1 >= N_NODES) c1 = N_NODES - 1;
    g_row[e]     = (int)r0;
    g_row[e + 1] = (int)r1;
    g_col[e]     = (int)c0;
    g_col[e + 1] = (int)c1;
    atomicAdd(&g_deg[(int)c0], 1);
    atomicAdd(&g_deg[(int)c1], 1);
}

// ---------------- CSR build: scan + scatter -----------------------------------
__global__ void __launch_bounds__(256) scan1_kernel() {
    __shared__ int warp_sums[8];
    int b   = blockIdx.x;
    int tid = threadIdx.x;
    int base = b * SCAN_CHUNK + tid * 4;

    int v0 = 0, v1 = 0, v2 = 0, v3 = 0;
    if (base + 0 < N_NODES) v0 = g_deg[base + 0] - 1;
    if (base + 1 < N_NODES) v1 = g_deg[base + 1] - 1;
    if (base + 2 < N_NODES) v2 = g_deg[base + 2] - 1;
    if (base + 3 < N_NODES) v3 = g_deg[base + 3] - 1;
    int tsum = v0 + v1 + v2 + v3;

    int lane = tid & 31, wid = tid >> 5;
    int s = tsum;
    #pragma unroll
    for (int off = 1; off < 32; off <<= 1) {
        int t = __shfl_up_sync(0xffffffffu, s, off);
        if (lane >= off) s += t;
    }
    if (lane == 31) warp_sums[wid] = s;
    __syncthreads();
    if (tid == 0) {
        int acc = 0;
        #pragma unroll
        for (int j = 0; j < 8; j++) { int t = warp_sums[j]; warp_sums[j] = acc; acc += t; }
        g_bsum[b] = acc;
    }
    __syncthreads();

    int excl = warp_sums[wid] + (s - tsum);
    if (base + 0 < N_NODES) g_start[base + 0] = excl; excl += v0;
    if (base + 1 < N_NODES) g_start[base + 1] = excl; excl += v1;
    if (base + 2 < N_NODES) g_start[base + 2] = excl; excl += v2;
    if (base + 3 < N_NODES) g_start[base + 3] = excl;
}

// parallel exclusive scan of the 98 block sums
__global__ void scan2_kernel() {
    __shared__ int ws[4];
    int tid = threadIdx.x;
    int v = (tid < SCAN_BLOCKS) ? g_bsum[tid] : 0;
    int lane = tid & 31, w = tid >> 5;
    int s = v;
    #pragma unroll
    for (int off = 1; off < 32; off <<= 1) {
        int t = __shfl_up_sync(0xffffffffu, s, off);
        if (lane >= off) s += t;
    }
    if (lane == 31) ws[w] = s;
    __syncthreads();
    int add = 0;
    #pragma unroll
    for (int j = 0; j < 4; j++) if (j < w) add += ws[j];
    s += add;
    if (tid < SCAN_BLOCKS) g_bsum[tid] = s - v;   // exclusive
}

// scan3 + dinv fused
__global__ void scan3_kernel() {
    int i = blockIdx.x * blockDim.x + threadIdx.x;
    if (i < N_NODES) {
        int v = g_start[i] + g_bsum[i / SCAN_CHUNK];
        g_start[i] = v;
        g_cur[i]   = v;
        g_dinv[i]  = rsqrtf((float)g_deg[i]);
    }
    if (i == 0) g_start[N_NODES] = N_EDGES;
}

__global__ void scatter_kernel() {
    int e = blockIdx.x * blockDim.x + threadIdx.x;
    if (e >= N_EDGES) return;
    int c = g_col[e];
    int pos = atomicAdd(&g_cur[c], 1);
    g_csr[pos] = g_row[e];
}

// ---------------- layer-1 GEMM (8x8 register tile): hs = dinv * (x @ W1) -----
// Forked stream; depends only on g_deg (dinv inline).
#define XS1_STRIDE 133
#define G1_SMEM (IN_CH*HID_CH*4 + 128*XS1_STRIDE*4)   // 100864
__global__ void __launch_bounds__(128) gemm1_kernel(
    const float* __restrict__ x, const float* __restrict__ W1)
{
    extern __shared__ float smem[];
    float* Wp = smem;                       // [128][64]
    float* xs = smem + IN_CH * HID_CH;      // [128][133]
    int tid = threadIdx.x;
    int row0 = blockIdx.x * 128;

    for (int i = tid; i < (IN_CH * HID_CH) / 4; i += 128)
        ((float4*)Wp)[i] = ((const float4*)W1)[i];

    for (int i = tid; i < 128 * 32; i += 128) {
        int r  = i >> 5;
        int k4 = (i & 31) * 4;
        int gr = row0 + r;
        float4 v = make_float4(0.f, 0.f, 0.f, 0.f);
        if (gr < N_NODES)
            v = ((const float4*)(x + (size_t)gr * IN_CH))[k4 >> 2];
        float* p = xs + r * XS1_STRIDE + k4;
        p[0] = v.x; p[1] = v.y; p[2] = v.z; p[3] = v.w;
    }
    __syncthreads();

    int cg = tid & 7;
    int rg = tid >> 3;
    const float* xrow = xs + rg * 8 * XS1_STRIDE;

    float acc[8][8];
    #pragma unroll
    for (int j = 0; j < 8; j++)
        #pragma unroll
        for (int c = 0; c < 8; c++) acc[j][c] = 0.f;

    #pragma unroll 4
    for (int k = 0; k < IN_CH; k++) {
        float4 wa = *(const float4*)&Wp[k * HID_CH + cg * 8];
        float4 wb = *(const float4*)&Wp[k * HID_CH + cg * 8 + 4];
        float xv[8];
        #pragma unroll
        for (int j = 0; j < 8; j++) xv[j] = xrow[j * XS1_STRIDE + k];
        #pragma unroll
        for (int j = 0; j < 8; j++) {
            acc[j][0] = fmaf(xv[j], wa.x, acc[j][0]);
            acc[j][1] = fmaf(xv[j], wa.y, acc[j][1]);
            acc[j][2] = fmaf(xv[j], wa.z, acc[j][2]);
            acc[j][3] = fmaf(xv[j], wa.w, acc[j][3]);
            acc[j][4] = fmaf(xv[j], wb.x, acc[j][4]);
            acc[j][5] = fmaf(xv[j], wb.y, acc[j][5]);
            acc[j][6] = fmaf(xv[j], wb.z, acc[j][6]);
            acc[j][7] = fmaf(xv[j], wb.w, acc[j][7]);
        }
    }

    #pragma unroll
    for (int j = 0; j < 8; j++) {
        int gr = row0 + rg * 8 + j;
        if (gr < N_NODES) {
            float dv = rsqrtf((float)g_deg[gr]);
            float4 o0 = make_float4(acc[j][0]*dv, acc[j][1]*dv, acc[j][2]*dv, acc[j][3]*dv);
            float4 o1 = make_float4(acc[j][4]*dv, acc[j][5]*dv, acc[j][6]*dv, acc[j][7]*dv);
            ((float4*)g_hs)[(size_t)gr * 16 + cg * 2 + 0] = o0;
            ((float4*)g_hs)[(size_t)gr * 16 + cg * 2 + 1] = o1;
        }
    }
}

// ---------------- fused agg1 + gemm2 ------------------------------------------
// Block = 256 threads, 128 nodes. Phase 1: gather-aggregate from g_hs, apply
// dinv/b1/relu, write h1 tile to smem. Phase 2: h1 @ W2 (*dinv) -> g_h2.
// smem: Wp[64*64] 16KB | hs[128][65] 33.28KB  = 49664 B
#define H1_STRIDE 65
#define FG_SMEM (HID_CH*OUT_CH*4 + 128*H1_STRIDE*4)
__global__ void __launch_bounds__(256) agg1_gemm2_kernel(
    const float* __restrict__ b1, const float* __restrict__ W2)
{
    extern __shared__ float smem[];
    float* Wp = smem;                       // [64][64]
    float* hs = smem + HID_CH * OUT_CH;     // [128][65]
    int tid = threadIdx.x;
    int row0 = blockIdx.x * 128;

    // stage W2 (independent; overlaps with gather latency below)
    for (int i = tid; i < (HID_CH * OUT_CH) / 4; i += 256)
        ((float4*)Wp)[i] = ((const float4*)W2)[i];

    // ---- phase 1: aggregate 128 nodes (16 threads/node, 8 node-batches) ----
    const float4* s4 = (const float4*)g_hs;
    int q  = tid & 15;
    int r0t = tid >> 4;                     // 0..15
    float4 bv = __ldg(((const float4*)b1) + q);

    #pragma unroll
    for (int sub = 0; sub < 8; sub++) {
        int r = r0t + sub * 16;             // local row 0..127
        int n = row0 + r;
        float sx = 0.f, sy = 0.f, sz = 0.f, sw = 0.f;
        float dv = 0.f;
        if (n < N_NODES) {
            float4 a = s4[(size_t)n * 16 + q];      // self-loop term
            sx = a.x; sy = a.y; sz = a.z; sw = a.w;
            int i   = g_start[n];
            int end = g_start[n + 1];
            for (; i + 3 < end; i += 4) {
                int e0 = g_csr[i], e1 = g_csr[i + 1];
                int e2 = g_csr[i + 2], e3 = g_csr[i + 3];
                float4 v0 = s4[(size_t)e0 * 16 + q];
                float4 v1 = s4[(size_t)e1 * 16 + q];
                float4 v2 = s4[(size_t)e2 * 16 + q];
                float4 v3 = s4[(size_t)e3 * 16 + q];
                sx += v0.x + v1.x + v2.x + v3.x;
                sy += v0.y + v1.y + v2.y + v3.y;
                sz += v0.z + v1.z + v2.z + v3.z;
                sw += v0.w + v1.w + v2.w + v3.w;
            }
            for (; i < end; i++) {
                int e0 = g_csr[i];
                float4 v0 = s4[(size_t)e0 * 16 + q];
                sx += v0.x; sy += v0.y; sz += v0.z; sw += v0.w;
            }
            dv = g_dinv[n];
        }
        float* p = hs + r * H1_STRIDE + q * 4;
        p[0] = fmaxf(fmaf(dv, sx, bv.x), 0.f);
        p[1] = fmaxf(fmaf(dv, sy, bv.y), 0.f);
        p[2] = fmaxf(fmaf(dv, sz, bv.z), 0.f);
        p[3] = fmaxf(fmaf(dv, sw, bv.w), 0.f);
    }
    __syncthreads();

    // ---- phase 2: GEMM h1[128][64] @ W2[64][64], thread tile 4x8 ----
    int cg = tid & 7;                       // 8 col-groups of 8
    int rg = tid >> 3;                      // 32 row-groups of 4
    const float* xrow = hs + rg * 4 * H1_STRIDE;

    float acc[4][8];
    #pragma unroll
    for (int j = 0; j < 4; j++)
        #pragma unroll
        for (int c = 0; c < 8; c++) acc[j][c] = 0.f;

    #pragma unroll 4
    for (int k = 0; k < HID_CH; k++) {
        float4 wa = *(const float4*)&Wp[k * OUT_CH + cg * 8];
        float4 wb = *(const float4*)&Wp[k * OUT_CH + cg * 8 + 4];
        float xv[4];
        #pragma unroll
        for (int j = 0; j < 4; j++) xv[j] = xrow[j * H1_STRIDE + k];
        #pragma unroll
        for (int j = 0; j < 4; j++) {
            acc[j][0] = fmaf(xv[j], wa.x, acc[j][0]);
            acc[j][1] = fmaf(xv[j], wa.y, acc[j][1]);
            acc[j][2] = fmaf(xv[j], wa.z, acc[j][2]);
            acc[j][3] = fmaf(xv[j], wa.w, acc[j][3]);
            acc[j][4] = fmaf(xv[j], wb.x, acc[j][4]);
            acc[j][5] = fmaf(xv[j], wb.y, acc[j][5]);
            acc[j][6] = fmaf(xv[j], wb.z, acc[j][6]);
            acc[j][7] = fmaf(xv[j], wb.w, acc[j][7]);
        }
    }

    #pragma unroll
    for (int j = 0; j < 4; j++) {
        int gr = row0 + rg * 4 + j;
        if (gr < N_NODES) {
            float dv = g_dinv[gr];
            float4 o0 = make_float4(acc[j][0]*dv, acc[j][1]*dv, acc[j][2]*dv, acc[j][3]*dv);
            float4 o1 = make_float4(acc[j][4]*dv, acc[j][5]*dv, acc[j][6]*dv, acc[j][7]*dv);
            ((float4*)g_h2)[(size_t)gr * 16 + cg * 2 + 0] = o0;
            ((float4*)g_h2)[(size_t)gr * 16 + cg * 2 + 1] = o1;
        }
    }
}

// ---------------- layer-2 aggregation + final epilogue -----------------------
__global__ void __launch_bounds__(256) agg2_kernel(
    float* __restrict__ outp, const float* __restrict__ b2)
{
    int t = blockIdx.x * blockDim.x + threadIdx.x;
    int n = t >> 4;
    int q = t & 15;
    if (n >= N_NODES) return;
    const float4* s4 = (const float4*)g_h2;

    float4 a = s4[(size_t)n * 16 + q];
    float sx = a.x, sy = a.y, sz = a.z, sw = a.w;

    int i   = g_start[n];
    int end = g_start[n + 1];
    for (; i + 3 < end; i += 4) {
        int e0 = g_csr[i], e1 = g_csr[i + 1];
        int e2 = g_csr[i + 2], e3 = g_csr[i + 3];
        float4 v0 = s4[(size_t)e0 * 16 + q];
        float4 v1 = s4[(size_t)e1 * 16 + q];
        float4 v2 = s4[(size_t)e2 * 16 + q];
        float4 v3 = s4[(size_t)e3 * 16 + q];
        sx += v0.x + v1.x + v2.x + v3.x;
        sy += v0.y + v1.y + v2.y + v3.y;
        sz += v0.z + v1.z + v2.z + v3.z;
        sw += v0.w + v1.w + v2.w + v3.w;
    }
    for (; i < end; i++) {
        int e0 = g_csr[i];
        float4 v0 = s4[(size_t)e0 * 16 + q];
        sx += v0.x; sy += v0.y; sz += v0.z; sw += v0.w;
    }
    float dv = g_dinv[n];
    float4 bb = ((const float4*)b2)[q];
    float4 o;
    o.x = fmaf(dv, sx, bb.x);
    o.y = fmaf(dv, sy, bb.y);
    o.z = fmaf(dv, sz, bb.z);
    o.w = fmaf(dv, sw, bb.w);
    ((float4*)outp)[(size_t)n * 16 + q] = o;
}

extern "C" void kernel_launch(void* const* d_in, const int* in_sizes, int n_in,
                              void* d_out, int out_size)
{
    // ---- identify inputs by element count ----
    const float* x  = nullptr;
    const void*  ei = nullptr;
    const float* W1 = nullptr;
    const float* b1 = nullptr;
    const float* W2 = nullptr;
    const float* b2 = nullptr;
    for (int i = 0; i < n_in; i++) {
        long long s = in_sizes[i];
        if      (s == (long long)N_NODES * IN_CH) x  = (const float*)d_in[i];
        else if (s == 2LL * N_EDGES)              ei = d_in[i];
        else if (s == (long long)IN_CH * HID_CH)  W1 = (const float*)d_in[i];
        else if (s == (long long)HID_CH * OUT_CH) W2 = (const float*)d_in[i];
        else if (s == HID_CH) { if (!b1) b1 = (const float*)d_in[i];
                                else     b2 = (const float*)d_in[i]; }
    }
    if (!x || !ei || !W1 || !b1 || !W2 || !b2) {
        x  = (const float*)d_in[0];
        ei = d_in[1];
        W1 = (const float*)d_in[2];
        b1 = (const float*)d_in[3];
        W2 = (const float*)d_in[4];
        b2 = (const float*)d_in[5];
    }
    float* outp = (float*)d_out;

    static cudaStream_t sB = nullptr;
    static cudaEvent_t  evA = nullptr, evB = nullptr;
    if (!sB) {
        cudaStreamCreateWithFlags(&sB, cudaStreamNonBlocking);
        cudaEventCreateWithFlags(&evA, cudaEventDisableTiming);
        cudaEventCreateWithFlags(&evB, cudaEventDisableTiming);
        cudaFuncSetAttribute(gemm1_kernel,
                             cudaFuncAttributeMaxDynamicSharedMemorySize, G1_SMEM);
        cudaFuncSetAttribute(agg1_gemm2_kernel,
                             cudaFuncAttributeMaxDynamicSharedMemorySize, FG_SMEM);
    }

    const int AGG_BLOCKS  = (N_NODES * 16) / 256;    // 6250
    const int GEMM_BLOCKS = (N_NODES + 127) / 128;   // 782

    // preprocessing head (main stream)
    probe_init_kernel<<<(N_NODES + 255) / 256, 256>>>(ei);
    convert_count_kernel<<<(N_EDGES / 2 + 255) / 256, 256>>>(ei);

    // fork: gemm1 (needs only g_deg + x/W1) runs concurrent with CSR build
    cudaEventRecord(evA, 0);
    cudaStreamWaitEvent(sB, evA, 0);
    gemm1_kernel<<<GEMM_BLOCKS, 128, G1_SMEM, sB>>>(x, W1);
    cudaEventRecord(evB, sB);

    // CSR build (main stream)
    scan1_kernel<<<SCAN_BLOCKS, 256>>>();
    scan2_kernel<<<1, 128>>>();
    scan3_kernel<<<(N_NODES + 255) / 256, 256>>>();
    scatter_kernel<<<(N_EDGES + 255) / 256, 256>>>();

    // join: fused agg1+gemm2 needs gemm1 (g_hs) and scatter (g_csr/g_start)
    cudaStreamWaitEvent(0, evB, 0);
    agg1_gemm2_kernel<<<GEMM_BLOCKS, 256, FG_SMEM>>>(b1, W2);

    // layer-2 aggregation + epilogue
    agg2_kernel<<<AGG_BLOCKS, 256>>>(outp, b2);
}

// round 13
// speedup vs baseline: 1.0700x; 1.0700x over previous
#include <cuda_runtime.h>
#include <cuda_bf16.h>

#define N_NODES 100000
#define N_EDGES 1600000
#define IN_CH 128
#define HID_CH 64
#define OUT_CH 64

#define SCAN_CHUNK 1024
#define SCAN_BLOCKS ((N_NODES + SCAN_CHUNK - 1) / SCAN_CHUNK)   // 98

#define NSPLIT 50048   // = 391*128 = 3128*16 ; exact block boundary for both kernels

// ---------------- scratch (device globals; device-code access ONLY) ---------
__device__ int   g_idx64;
__device__ int   g_row[N_EDGES];
__device__ int   g_col[N_EDGES];
__device__ int   g_csr[N_EDGES];            // source indices grouped by dst
__device__ int   g_deg[N_NODES];            // 1 + in-degree (self-loop incl.)
__device__ int   g_start[N_NODES + 1];      // CSR offsets (edges only)
__device__ int   g_cur[N_NODES];            // scatter cursors
__device__ int   g_bsum[SCAN_BLOCKS];
__device__ float g_dinv[N_NODES];
__device__ float g_hs [N_NODES * HID_CH];   // dinv-scaled layer-1 msg source
__device__ float g_acc[N_NODES * HID_CH];   // layer-1 aggregation result
__device__ float g_h2 [N_NODES * HID_CH];   // layer-2 msg source

// ---------------- probe (block 0) + deg init (all blocks), one launch --------
__global__ void probe_init_kernel(const void* ei) {
    int i = blockIdx.x * blockDim.x + threadIdx.x;
    if (i < N_NODES) g_deg[i] = 1;   // self-loop
    if (blockIdx.x == 0) {
        __shared__ int ok;
        if (threadIdx.x == 0) ok = 1;
        __syncthreads();
        const long long* p = (const long long*)ei;
        for (int j = threadIdx.x; j < 1024; j += blockDim.x) {
            long long v = p[j];
            if (v < 0 || v >= N_NODES) ok = 0;
        }
        __syncthreads();
        if (threadIdx.x == 0) g_idx64 = ok;
    }
}

// fused convert + clamp + degree histogram; 2 edges per thread (vector loads)
__global__ void convert_count_kernel(const void* ei) {
    int t = blockIdx.x * blockDim.x + threadIdx.x;
    int e = t * 2;
    if (e >= N_EDGES) return;
    long long r0, r1, c0, c1;
    if (g_idx64) {
        const longlong2* p = (const longlong2*)ei;
        longlong2 rr = p[t];
        longlong2 cc = p[(N_EDGES / 2) + t];
        r0 = rr.x; r1 = rr.y; c0 = cc.x; c1 = cc.y;
    } else {
        const int2* p = (const int2*)ei;
        int2 rr = p[t];
        int2 cc = p[(N_EDGES / 2) + t];
        r0 = rr.x; r1 = rr.y; c0 = cc.x; c1 = cc.y;
    }
    if (r0 < 0) r0 = 0; if (r0 >= N_NODES) r0 = N_NODES - 1;
    if (r1 < 0) r1 = 0; if (r1 >= N_NODES) r1 = N_NODES - 1;
    if (c0 < 0) c0 = 0; if (c0 >= N_NODES) c0 = N_NODES - 1;
    if (c1 < 0) c1 = 0; if (c1 >= N_NODES) c1 = N_NODES - 1;
    g_row[e]     = (int)r0;
    g_row[e + 1] = (int)r1;
    g_col[e]     = (int)c0;
    g_col[e + 1] = (int)c1;
    atomicAdd(&g_deg[(int)c0], 1);
    atomicAdd(&g_deg[(int)c1], 1);
}

// ---------------- CSR build: scan + scatter -----------------------------------
__global__ void __launch_bounds__(256) scan1_kernel() {
    __shared__ int warp_sums[8];
    int b   = blockIdx.x;
    int tid = threadIdx.x;
    int base = b * SCAN_CHUNK + tid * 4;

    int v0 = 0, v1 = 0, v2 = 0, v3 = 0;
    if (base + 0 < N_NODES) v0 = g_deg[base + 0] - 1;
    if (base + 1 < N_NODES) v1 = g_deg[base + 1] - 1;
    if (base + 2 < N_NODES) v2 = g_deg[base + 2] - 1;
    if (base + 3 < N_NODES) v3 = g_deg[base + 3] - 1;
    int tsum = v0 + v1 + v2 + v3;

    int lane = tid & 31, wid = tid >> 5;
    int s = tsum;
    #pragma unroll
    for (int off = 1; off < 32; off <<= 1) {
        int t = __shfl_up_sync(0xffffffffu, s, off);
        if (lane >= off) s += t;
    }
    if (lane == 31) warp_sums[wid] = s;
    __syncthreads();
    if (tid == 0) {
        int acc = 0;
        #pragma unroll
        for (int j = 0; j < 8; j++) { int t = warp_sums[j]; warp_sums[j] = acc; acc += t; }
        g_bsum[b] = acc;
    }
    __syncthreads();

    int excl = warp_sums[wid] + (s - tsum);
    if (base + 0 < N_NODES) g_start[base + 0] = excl; excl += v0;
    if (base + 1 < N_NODES) g_start[base + 1] = excl; excl += v1;
    if (base + 2 < N_NODES) g_start[base + 2] = excl; excl += v2;
    if (base + 3 < N_NODES) g_start[base + 3] = excl;
}

// parallel exclusive scan of the 98 block sums
__global__ void scan2_kernel() {
    __shared__ int ws[4];
    int tid = threadIdx.x;
    int v = (tid < SCAN_BLOCKS) ? g_bsum[tid] : 0;
    int lane = tid & 31, w = tid >> 5;
    int s = v;
    #pragma unroll
    for (int off = 1; off < 32; off <<= 1) {
        int t = __shfl_up_sync(0xffffffffu, s, off);
        if (lane >= off) s += t;
    }
    if (lane == 31) ws[w] = s;
    __syncthreads();
    int add = 0;
    #pragma unroll
    for (int j = 0; j < 4; j++) if (j < w) add += ws[j];
    s += add;
    if (tid < SCAN_BLOCKS) g_bsum[tid] = s - v;   // exclusive
}

// scan3 + dinv fused
__global__ void scan3_kernel() {
    int i = blockIdx.x * blockDim.x + threadIdx.x;
    if (i < N_NODES) {
        int v = g_start[i] + g_bsum[i / SCAN_CHUNK];
        g_start[i] = v;
        g_cur[i]   = v;
        g_dinv[i]  = rsqrtf((float)g_deg[i]);
    }
    if (i == 0) g_start[N_NODES] = N_EDGES;
}

__global__ void scatter_kernel() {
    int e = blockIdx.x * blockDim.x + threadIdx.x;
    if (e >= N_EDGES) return;
    int c = g_col[e];
    int pos = atomicAdd(&g_cur[c], 1);
    g_csr[pos] = g_row[e];
}

// ---------------- layer-1 GEMM (8x8 register tile): hs = dinv * (x @ W1) -----
// Forked stream; depends only on g_deg (dinv inline).
#define XS1_STRIDE 133
#define G1_SMEM (IN_CH*HID_CH*4 + 128*XS1_STRIDE*4)   // 100864
__global__ void __launch_bounds__(128) gemm1_kernel(
    const float* __restrict__ x, const float* __restrict__ W1)
{
    extern __shared__ float smem[];
    float* Wp = smem;                       // [128][64]
    float* xs = smem + IN_CH * HID_CH;      // [128][133]
    int tid = threadIdx.x;
    int row0 = blockIdx.x * 128;

    for (int i = tid; i < (IN_CH * HID_CH) / 4; i += 128)
        ((float4*)Wp)[i] = ((const float4*)W1)[i];

    for (int i = tid; i < 128 * 32; i += 128) {
        int r  = i >> 5;
        int k4 = (i & 31) * 4;
        int gr = row0 + r;
        float4 v = make_float4(0.f, 0.f, 0.f, 0.f);
        if (gr < N_NODES)
            v = ((const float4*)(x + (size_t)gr * IN_CH))[k4 >> 2];
        float* p = xs + r * XS1_STRIDE + k4;
        p[0] = v.x; p[1] = v.y; p[2] = v.z; p[3] = v.w;
    }
    __syncthreads();

    int cg = tid & 7;
    int rg = tid >> 3;
    const float* xrow = xs + rg * 8 * XS1_STRIDE;

    float acc[8][8];
    #pragma unroll
    for (int j = 0; j < 8; j++)
        #pragma unroll
        for (int c = 0; c < 8; c++) acc[j][c] = 0.f;

    #pragma unroll 4
    for (int k = 0; k < IN_CH; k++) {
        float4 wa = *(const float4*)&Wp[k * HID_CH + cg * 8];
        float4 wb = *(const float4*)&Wp[k * HID_CH + cg * 8 + 4];
        float xv[8];
        #pragma unroll
        for (int j = 0; j < 8; j++) xv[j] = xrow[j * XS1_STRIDE + k];
        #pragma unroll
        for (int j = 0; j < 8; j++) {
            acc[j][0] = fmaf(xv[j], wa.x, acc[j][0]);
            acc[j][1] = fmaf(xv[j], wa.y, acc[j][1]);
            acc[j][2] = fmaf(xv[j], wa.z, acc[j][2]);
            acc[j][3] = fmaf(xv[j], wa.w, acc[j][3]);
            acc[j][4] = fmaf(xv[j], wb.x, acc[j][4]);
            acc[j][5] = fmaf(xv[j], wb.y, acc[j][5]);
            acc[j][6] = fmaf(xv[j], wb.z, acc[j][6]);
            acc[j][7] = fmaf(xv[j], wb.w, acc[j][7]);
        }
    }

    #pragma unroll
    for (int j = 0; j < 8; j++) {
        int gr = row0 + rg * 8 + j;
        if (gr < N_NODES) {
            float dv = rsqrtf((float)g_deg[gr]);
            float4 o0 = make_float4(acc[j][0]*dv, acc[j][1]*dv, acc[j][2]*dv, acc[j][3]*dv);
            float4 o1 = make_float4(acc[j][4]*dv, acc[j][5]*dv, acc[j][6]*dv, acc[j][7]*dv);
            ((float4*)g_hs)[(size_t)gr * 16 + cg * 2 + 0] = o0;
            ((float4*)g_hs)[(size_t)gr * 16 + cg * 2 + 1] = o1;
        }
    }
}

// ---------------- gather-side aggregation (atomic-free, range-split) ---------
// 16 threads/node; node n = base + t/16, processes nodes [base, limit).
__global__ void __launch_bounds__(256) agg1_kernel(int base, int limit)
{
    int t = blockIdx.x * blockDim.x + threadIdx.x;
    int n = base + (t >> 4);
    int q = t & 15;
    if (n >= limit) return;
    const float4* s4 = (const float4*)g_hs;

    float4 a = s4[(size_t)n * 16 + q];       // self-loop term
    float sx = a.x, sy = a.y, sz = a.z, sw = a.w;

    int i   = g_start[n];
    int end = g_start[n + 1];
    for (; i + 3 < end; i += 4) {
        int e0 = g_csr[i],     e1 = g_csr[i + 1];
        int e2 = g_csr[i + 2], e3 = g_csr[i + 3];
        float4 v0 = s4[(size_t)e0 * 16 + q];
        float4 v1 = s4[(size_t)e1 * 16 + q];
        float4 v2 = s4[(size_t)e2 * 16 + q];
        float4 v3 = s4[(size_t)e3 * 16 + q];
        sx += v0.x + v1.x + v2.x + v3.x;
        sy += v0.y + v1.y + v2.y + v3.y;
        sz += v0.z + v1.z + v2.z + v3.z;
        sw += v0.w + v1.w + v2.w + v3.w;
    }
    for (; i < end; i++) {
        int e0 = g_csr[i];
        float4 v0 = s4[(size_t)e0 * 16 + q];
        sx += v0.x; sy += v0.y; sz += v0.z; sw += v0.w;
    }
    ((float4*)g_acc)[(size_t)n * 16 + q] = make_float4(sx, sy, sz, sw);
}

// ---------------- layer-2 GEMM (8x8, range-split): h2 = dinv*(relu(...)@W2) --
#define XS2_STRIDE 69
#define G2_SMEM (HID_CH*OUT_CH*4 + 128*XS2_STRIDE*4)   // 51712
__global__ void __launch_bounds__(128) gemm2_kernel(
    const float* __restrict__ b1, const float* __restrict__ W2, int base)
{
    extern __shared__ float smem[];
    float* Wp = smem;                       // [64][64]
    float* xs = smem + HID_CH * OUT_CH;     // [128][69]
    int tid = threadIdx.x;
    int row0 = base + blockIdx.x * 128;

    for (int i = tid; i < (HID_CH * OUT_CH) / 4; i += 128)
        ((float4*)Wp)[i] = ((const float4*)W2)[i];

    for (int i = tid; i < 128 * 16; i += 128) {
        int r  = i >> 4;
        int k4 = (i & 15) * 4;
        int gr = row0 + r;
        float4 o = make_float4(0.f, 0.f, 0.f, 0.f);
        if (gr < N_NODES) {
            float dv = g_dinv[gr];
            float4 av = ((const float4*)g_acc)[(size_t)gr * 16 + (k4 >> 2)];
            float4 bv = __ldg(((const float4*)b1) + (k4 >> 2));
            o.x = fmaxf(fmaf(dv, av.x, bv.x), 0.f);
            o.y = fmaxf(fmaf(dv, av.y, bv.y), 0.f);
            o.z = fmaxf(fmaf(dv, av.z, bv.z), 0.f);
            o.w = fmaxf(fmaf(dv, av.w, bv.w), 0.f);
        }
        float* p = xs + r * XS2_STRIDE + k4;
        p[0] = o.x; p[1] = o.y; p[2] = o.z; p[3] = o.w;
    }
    __syncthreads();

    int cg = tid & 7;
    int rg = tid >> 3;
    const float* xrow = xs + rg * 8 * XS2_STRIDE;

    float acc[8][8];
    #pragma unroll
    for (int j = 0; j < 8; j++)
        #pragma unroll
        for (int c = 0; c < 8; c++) acc[j][c] = 0.f;

    #pragma unroll 4
    for (int k = 0; k < HID_CH; k++) {
        float4 wa = *(const float4*)&Wp[k * OUT_CH + cg * 8];
        float4 wb = *(const float4*)&Wp[k * OUT_CH + cg * 8 + 4];
        float xv[8];
        #pragma unroll
        for (int j = 0; j < 8; j++) xv[j] = xrow[j * XS2_STRIDE + k];
        #pragma unroll
        for (int j = 0; j < 8; j++) {
            acc[j][0] = fmaf(xv[j], wa.x, acc[j][0]);
            acc[j][1] = fmaf(xv[j], wa.y, acc[j][1]);
            acc[j][2] = fmaf(xv[j], wa.z, acc[j][2]);
            acc[j][3] = fmaf(xv[j], wa.w, acc[j][3]);
            acc[j][4] = fmaf(xv[j], wb.x, acc[j][4]);
            acc[j][5] = fmaf(xv[j], wb.y, acc[j][5]);
            acc[j][6] = fmaf(xv[j], wb.z, acc[j][6]);
            acc[j][7] = fmaf(xv[j], wb.w, acc[j][7]);
        }
    }

    #pragma unroll
    for (int j = 0; j < 8; j++) {
        int gr = row0 + rg * 8 + j;
        if (gr < N_NODES) {
            float dv = g_dinv[gr];
            float4 o0 = make_float4(acc[j][0]*dv, acc[j][1]*dv, acc[j][2]*dv, acc[j][3]*dv);
            float4 o1 = make_float4(acc[j][4]*dv, acc[j][5]*dv, acc[j][6]*dv, acc[j][7]*dv);
            ((float4*)g_h2)[(size_t)gr * 16 + cg * 2 + 0] = o0;
            ((float4*)g_h2)[(size_t)gr * 16 + cg * 2 + 1] = o1;
        }
    }
}

// ---------------- layer-2 aggregation + final epilogue -----------------------
__global__ void __launch_bounds__(256) agg2_kernel(
    float* __restrict__ outp, const float* __restrict__ b2)
{
    int t = blockIdx.x * blockDim.x + threadIdx.x;
    int n = t >> 4;
    int q = t & 15;
    if (n >= N_NODES) return;
    const float4* s4 = (const float4*)g_h2;

    float4 a = s4[(size_t)n * 16 + q];
    float sx = a.x, sy = a.y, sz = a.z, sw = a.w;

    int i   = g_start[n];
    int end = g_start[n + 1];
    for (; i + 3 < end; i += 4) {
        int e0 = g_csr[i],     e1 = g_csr[i + 1];
        int e2 = g_csr[i + 2], e3 = g_csr[i + 3];
        float4 v0 = s4[(size_t)e0 * 16 + q];
        float4 v1 = s4[(size_t)e1 * 16 + q];
        float4 v2 = s4[(size_t)e2 * 16 + q];
        float4 v3 = s4[(size_t)e3 * 16 + q];
        sx += v0.x + v1.x + v2.x + v3.x;
        sy += v0.y + v1.y + v2.y + v3.y;
        sz += v0.z + v1.z + v2.z + v3.z;
        sw += v0.w + v1.w + v2.w + v3.w;
    }
    for (; i < end; i++) {
        int e0 = g_csr[i];
        float4 v0 = s4[(size_t)e0 * 16 + q];
        sx += v0.x; sy += v0.y; sz += v0.z; sw += v0.w;
    }
    float dv = g_dinv[n];
    float4 bb = ((const float4*)b2)[q];
    float4 o;
    o.x = fmaf(dv, sx, bb.x);
    o.y = fmaf(dv, sy, bb.y);
    o.z = fmaf(dv, sz, bb.z);
    o.w = fmaf(dv, sw, bb.w);
    ((float4*)outp)[(size_t)n * 16 + q] = o;
}

extern "C" void kernel_launch(void* const* d_in, const int* in_sizes, int n_in,
                              void* d_out, int out_size)
{
    // ---- identify inputs by element count ----
    const float* x  = nullptr;
    const void*  ei = nullptr;
    const float* W1 = nullptr;
    const float* b1 = nullptr;
    const float* W2 = nullptr;
    const float* b2 = nullptr;
    for (int i = 0; i < n_in; i++) {
        long long s = in_sizes[i];
        if      (s == (long long)N_NODES * IN_CH) x  = (const float*)d_in[i];
        else if (s == 2LL * N_EDGES)              ei = d_in[i];
        else if (s == (long long)IN_CH * HID_CH)  W1 = (const float*)d_in[i];
        else if (s == (long long)HID_CH * OUT_CH) W2 = (const float*)d_in[i];
        else if (s == HID_CH) { if (!b1) b1 = (const float*)d_in[i];
                                else     b2 = (const float*)d_in[i]; }
    }
    if (!x || !ei || !W1 || !b1 || !W2 || !b2) {
        x  = (const float*)d_in[0];
        ei = d_in[1];
        W1 = (const float*)d_in[2];
        b1 = (const float*)d_in[3];
        W2 = (const float*)d_in[4];
        b2 = (const float*)d_in[5];
    }
    float* outp = (float*)d_out;

    static cudaStream_t sB = nullptr;
    static cudaEvent_t  evA = nullptr, evB = nullptr, evC = nullptr, evD = nullptr;
    if (!sB) {
        cudaStreamCreateWithFlags(&sB, cudaStreamNonBlocking);
        cudaEventCreateWithFlags(&evA, cudaEventDisableTiming);
        cudaEventCreateWithFlags(&evB, cudaEventDisableTiming);
        cudaEventCreateWithFlags(&evC, cudaEventDisableTiming);
        cudaEventCreateWithFlags(&evD, cudaEventDisableTiming);
        cudaFuncSetAttribute(gemm1_kernel,
                             cudaFuncAttributeMaxDynamicSharedMemorySize, G1_SMEM);
        cudaFuncSetAttribute(gemm2_kernel,
                             cudaFuncAttributeMaxDynamicSharedMemorySize, G2_SMEM);
    }

    const int AGG_BLOCKS   = (N_NODES * 16) / 256;          // 6250
    const int GEMM_BLOCKS  = (N_NODES + 127) / 128;         // 782
    const int AGG_LO       = (NSPLIT * 16) / 256;           // 3128
    const int AGG_HI       = ((N_NODES - NSPLIT) * 16 + 255) / 256;   // 3122
    const int G2_HALF      = NSPLIT / 128;                  // 391

    // preprocessing head (main stream)
    probe_init_kernel<<<(N_NODES + 255) / 256, 256>>>(ei);
    convert_count_kernel<<<(N_EDGES / 2 + 255) / 256, 256>>>(ei);

    // fork: gemm1 (needs only g_deg + x/W1) runs concurrent with CSR build
    cudaEventRecord(evA, 0);
    cudaStreamWaitEvent(sB, evA, 0);
    gemm1_kernel<<<GEMM_BLOCKS, 128, G1_SMEM, sB>>>(x, W1);
    cudaEventRecord(evB, sB);

    // CSR build (main stream)
    scan1_kernel<<<SCAN_BLOCKS, 256>>>();
    scan2_kernel<<<1, 128>>>();
    scan3_kernel<<<(N_NODES + 255) / 256, 256>>>();
    scatter_kernel<<<(N_EDGES + 255) / 256, 256>>>();

    // join gemm1, then range-split pipeline:
    //   main: agg1_lo -> agg1_hi -> gemm2_hi
    //   side: gemm2_lo (after agg1_lo), concurrent with agg1_hi
    cudaStreamWaitEvent(0, evB, 0);
    agg1_kernel<<<AGG_LO, 256>>>(0, NSPLIT);
    cudaEventRecord(evC, 0);
    agg1_kernel<<<AGG_HI, 256>>>(NSPLIT, N_NODES);

    cudaStreamWaitEvent(sB, evC, 0);
    gemm2_kernel<<<G2_HALF, 128, G2_SMEM, sB>>>(b1, W2, 0);
    cudaEventRecord(evD, sB);

    gemm2_kernel<<<G2_HALF, 128, G2_SMEM>>>(b1, W2, NSPLIT);

    // join gemm2_lo, then layer-2 aggregation + epilogue
    cudaStreamWaitEvent(0, evD, 0);
    agg2_kernel<<<AGG_BLOCKS, 256>>>(outp, b2);
}

// round 14
// speedup vs baseline: 1.0745x; 1.0042x over previous
#include <cuda_runtime.h>
#include <cuda_bf16.h>

#define N_NODES 100000
#define N_EDGES 1600000
#define IN_CH 128
#define HID_CH 64
#define OUT_CH 64

#define SCAN_CHUNK 1024
#define SCAN_BLOCKS ((N_NODES + SCAN_CHUNK - 1) / SCAN_CHUNK)   // 98

// ---------------- scratch (device globals; device-code access ONLY) ---------
__device__ int   g_idx64;
__device__ int   g_row[N_EDGES];
__device__ int   g_col[N_EDGES];
__device__ int   g_rank[N_EDGES];           // rank among same-col edges
__device__ int   g_csr[N_EDGES];            // source indices grouped by dst
__device__ int   g_deg[N_NODES];            // 1 + in-degree (self-loop incl.)
__device__ int   g_start[N_NODES + 1];      // CSR offsets (edges only)
__device__ int   g_bsum[SCAN_BLOCKS];
__device__ float g_dinv[N_NODES];
__device__ float g_hs [N_NODES * HID_CH];   // dinv-scaled layer-1 msg source
__device__ float g_acc[N_NODES * HID_CH];   // layer-1 aggregation result
__device__ float g_h2 [N_NODES * HID_CH];   // layer-2 msg source

// ---------------- probe (block 0) + deg init (all blocks), one launch --------
__global__ void probe_init_kernel(const void* ei) {
    int i = blockIdx.x * blockDim.x + threadIdx.x;
    if (i < N_NODES) g_deg[i] = 1;   // self-loop
    if (blockIdx.x == 0) {
        __shared__ int ok;
        if (threadIdx.x == 0) ok = 1;
        __syncthreads();
        const long long* p = (const long long*)ei;
        for (int j = threadIdx.x; j < 1024; j += blockDim.x) {
            long long v = p[j];
            if (v < 0 || v >= N_NODES) ok = 0;
        }
        __syncthreads();
        if (threadIdx.x == 0) g_idx64 = ok;
    }
}

// fused convert + clamp + degree histogram + per-edge rank; 2 edges/thread
__global__ void convert_count_kernel(const void* ei) {
    int t = blockIdx.x * blockDim.x + threadIdx.x;
    int e = t * 2;
    if (e >= N_EDGES) return;
    long long r0, r1, c0, c1;
    if (g_idx64) {
        const longlong2* p = (const longlong2*)ei;
        longlong2 rr = p[t];
        longlong2 cc = p[(N_EDGES / 2) + t];
        r0 = rr.x; r1 = rr.y; c0 = cc.x; c1 = cc.y;
    } else {
        const int2* p = (const int2*)ei;
        int2 rr = p[t];
        int2 cc = p[(N_EDGES / 2) + t];
        r0 = rr.x; r1 = rr.y; c0 = cc.x; c1 = cc.y;
    }
    if (r0 < 0) r0 = 0; if (r0 >= N_NODES) r0 = N_NODES - 1;
    if (r1 < 0) r1 = 0; if (r1 >= N_NODES) r1 = N_NODES - 1;
    if (c0 < 0) c0 = 0; if (c0 >= N_NODES) c0 = N_NODES - 1;
    if (c1 < 0) c1 = 0; if (c1 >= N_NODES) c1 = N_NODES - 1;
    g_row[e]     = (int)r0;
    g_row[e + 1] = (int)r1;
    g_col[e]     = (int)c0;
    g_col[e + 1] = (int)c1;
    // deg starts at 1 (self-loop) -> rank among same-col edges = old - 1
    int o0 = atomicAdd(&g_deg[(int)c0], 1);
    int o1 = atomicAdd(&g_deg[(int)c1], 1);
    g_rank[e]     = o0 - 1;
    g_rank[e + 1] = o1 - 1;
}

// ---------------- CSR build: scan + atomic-free scatter -----------------------
__global__ void __launch_bounds__(256) scan1_kernel() {
    __shared__ int warp_sums[8];
    int b   = blockIdx.x;
    int tid = threadIdx.x;
    int base = b * SCAN_CHUNK + tid * 4;

    int v0 = 0, v1 = 0, v2 = 0, v3 = 0;
    if (base + 0 < N_NODES) v0 = g_deg[base + 0] - 1;
    if (base + 1 < N_NODES) v1 = g_deg[base + 1] - 1;
    if (base + 2 < N_NODES) v2 = g_deg[base + 2] - 1;
    if (base + 3 < N_NODES) v3 = g_deg[base + 3] - 1;
    int tsum = v0 + v1 + v2 + v3;

    int lane = tid & 31, wid = tid >> 5;
    int s = tsum;
    #pragma unroll
    for (int off = 1; off < 32; off <<= 1) {
        int t = __shfl_up_sync(0xffffffffu, s, off);
        if (lane >= off) s += t;
    }
    if (lane == 31) warp_sums[wid] = s;
    __syncthreads();
    if (tid == 0) {
        int acc = 0;
        #pragma unroll
        for (int j = 0; j < 8; j++) { int t = warp_sums[j]; warp_sums[j] = acc; acc += t; }
        g_bsum[b] = acc;
    }
    __syncthreads();

    int excl = warp_sums[wid] + (s - tsum);
    if (base + 0 < N_NODES) g_start[base + 0] = excl; excl += v0;
    if (base + 1 < N_NODES) g_start[base + 1] = excl; excl += v1;
    if (base + 2 < N_NODES) g_start[base + 2] = excl; excl += v2;
    if (base + 3 < N_NODES) g_start[base + 3] = excl;
}

// parallel exclusive scan of the 98 block sums
__global__ void scan2_kernel() {
    __shared__ int ws[4];
    int tid = threadIdx.x;
    int v = (tid < SCAN_BLOCKS) ? g_bsum[tid] : 0;
    int lane = tid & 31, w = tid >> 5;
    int s = v;
    #pragma unroll
    for (int off = 1; off < 32; off <<= 1) {
        int t = __shfl_up_sync(0xffffffffu, s, off);
        if (lane >= off) s += t;
    }
    if (lane == 31) ws[w] = s;
    __syncthreads();
    int add = 0;
    #pragma unroll
    for (int j = 0; j < 4; j++) if (j < w) add += ws[j];
    s += add;
    if (tid < SCAN_BLOCKS) g_bsum[tid] = s - v;   // exclusive
}

// scan3 + dinv fused (no cursor init needed anymore)
__global__ void scan3_kernel() {
    int i = blockIdx.x * blockDim.x + threadIdx.x;
    if (i < N_NODES) {
        g_start[i] = g_start[i] + g_bsum[i / SCAN_CHUNK];
        g_dinv[i]  = rsqrtf((float)g_deg[i]);
    }
    if (i == 0) g_start[N_NODES] = N_EDGES;
}

// atomic-free scatter: position precomputed from start + rank
__global__ void scatter_kernel() {
    int e = blockIdx.x * blockDim.x + threadIdx.x;
    if (e >= N_EDGES) return;
    int c = g_col[e];
    g_csr[g_start[c] + g_rank[e]] = g_row[e];
}

// ---------------- layer-1 GEMM (8x8 register tile): hs = dinv * (x @ W1) -----
// Forked stream; depends only on g_deg (dinv inline).
#define XS1_STRIDE 133
#define G1_SMEM (IN_CH*HID_CH*4 + 128*XS1_STRIDE*4)   // 100864
__global__ void __launch_bounds__(128) gemm1_kernel(
    const float* __restrict__ x, const float* __restrict__ W1)
{
    extern __shared__ float smem[];
    float* Wp = smem;                       // [128][64]
    float* xs = smem + IN_CH * HID_CH;      // [128][133]
    int tid = threadIdx.x;
    int row0 = blockIdx.x * 128;

    for (int i = tid; i < (IN_CH * HID_CH) / 4; i += 128)
        ((float4*)Wp)[i] = ((const float4*)W1)[i];

    for (int i = tid; i < 128 * 32; i += 128) {
        int r  = i >> 5;
        int k4 = (i & 31) * 4;
        int gr = row0 + r;
        float4 v = make_float4(0.f, 0.f, 0.f, 0.f);
        if (gr < N_NODES)
            v = ((const float4*)(x + (size_t)gr * IN_CH))[k4 >> 2];
        float* p = xs + r * XS1_STRIDE + k4;
        p[0] = v.x; p[1] = v.y; p[2] = v.z; p[3] = v.w;
    }
    __syncthreads();

    int cg = tid & 7;
    int rg = tid >> 3;
    const float* xrow = xs + rg * 8 * XS1_STRIDE;

    float acc[8][8];
    #pragma unroll
    for (int j = 0; j < 8; j++)
        #pragma unroll
        for (int c = 0; c < 8; c++) acc[j][c] = 0.f;

    #pragma unroll 4
    for (int k = 0; k < IN_CH; k++) {
        float4 wa = *(const float4*)&Wp[k * HID_CH + cg * 8];
        float4 wb = *(const float4*)&Wp[k * HID_CH + cg * 8 + 4];
        float xv[8];
        #pragma unroll
        for (int j = 0; j < 8; j++) xv[j] = xrow[j * XS1_STRIDE + k];
        #pragma unroll
        for (int j = 0; j < 8; j++) {
            acc[j][0] = fmaf(xv[j], wa.x, acc[j][0]);
            acc[j][1] = fmaf(xv[j], wa.y, acc[j][1]);
            acc[j][2] = fmaf(xv[j], wa.z, acc[j][2]);
            acc[j][3] = fmaf(xv[j], wa.w, acc[j][3]);
            acc[j][4] = fmaf(xv[j], wb.x, acc[j][4]);
            acc[j][5] = fmaf(xv[j], wb.y, acc[j][5]);
            acc[j][6] = fmaf(xv[j], wb.z, acc[j][6]);
            acc[j][7] = fmaf(xv[j], wb.w, acc[j][7]);
        }
    }

    #pragma unroll
    for (int j = 0; j < 8; j++) {
        int gr = row0 + rg * 8 + j;
        if (gr < N_NODES) {
            float dv = rsqrtf((float)g_deg[gr]);
            float4 o0 = make_float4(acc[j][0]*dv, acc[j][1]*dv, acc[j][2]*dv, acc[j][3]*dv);
            float4 o1 = make_float4(acc[j][4]*dv, acc[j][5]*dv, acc[j][6]*dv, acc[j][7]*dv);
            ((float4*)g_hs)[(size_t)gr * 16 + cg * 2 + 0] = o0;
            ((float4*)g_hs)[(size_t)gr * 16 + cg * 2 + 1] = o1;
        }
    }
}

// ---------------- gather-side aggregation (atomic-free) ----------------------
__global__ void __launch_bounds__(256) agg1_kernel()
{
    int t = blockIdx.x * blockDim.x + threadIdx.x;
    int n = t >> 4;
    int q = t & 15;
    if (n >= N_NODES) return;
    const float4* s4 = (const float4*)g_hs;

    float4 a = s4[(size_t)n * 16 + q];       // self-loop term
    float sx = a.x, sy = a.y, sz = a.z, sw = a.w;

    int i   = g_start[n];
    int end = g_start[n + 1];
    for (; i + 1 < end; i += 2) {
        int r0 = g_csr[i];
        int r1 = g_csr[i + 1];
        float4 v0 = s4[(size_t)r0 * 16 + q];
        float4 v1 = s4[(size_t)r1 * 16 + q];
        sx += v0.x; sy += v0.y; sz += v0.z; sw += v0.w;
        sx += v1.x; sy += v1.y; sz += v1.z; sw += v1.w;
    }
    if (i < end) {
        int r0 = g_csr[i];
        float4 v0 = s4[(size_t)r0 * 16 + q];
        sx += v0.x; sy += v0.y; sz += v0.z; sw += v0.w;
    }
    ((float4*)g_acc)[(size_t)n * 16 + q] = make_float4(sx, sy, sz, sw);
}

// layer-2 aggregation fused with final epilogue: out = dinv[n]*sum + b2
__global__ void __launch_bounds__(256) agg2_kernel(
    float* __restrict__ outp, const float* __restrict__ b2)
{
    int t = blockIdx.x * blockDim.x + threadIdx.x;
    int n = t >> 4;
    int q = t & 15;
    if (n >= N_NODES) return;
    const float4* s4 = (const float4*)g_h2;

    float4 a = s4[(size_t)n * 16 + q];
    float sx = a.x, sy = a.y, sz = a.z, sw = a.w;

    int i   = g_start[n];
    int end = g_start[n + 1];
    for (; i + 1 < end; i += 2) {
        int r0 = g_csr[i];
        int r1 = g_csr[i + 1];
        float4 v0 = s4[(size_t)r0 * 16 + q];
        float4 v1 = s4[(size_t)r1 * 16 + q];
        sx += v0.x; sy += v0.y; sz += v0.z; sw += v0.w;
        sx += v1.x; sy += v1.y; sz += v1.z; sw += v1.w;
    }
    if (i < end) {
        int r0 = g_csr[i];
        float4 v0 = s4[(size_t)r0 * 16 + q];
        sx += v0.x; sy += v0.y; sz += v0.z; sw += v0.w;
    }
    float dv = g_dinv[n];
    float4 bb = ((const float4*)b2)[q];
    float4 o;
    o.x = fmaf(dv, sx, bb.x);
    o.y = fmaf(dv, sy, bb.y);
    o.z = fmaf(dv, sz, bb.z);
    o.w = fmaf(dv, sw, bb.w);
    ((float4*)outp)[(size_t)n * 16 + q] = o;
}

// ---------------- layer-2 GEMM (8x8): h2 = dinv * (relu(dinv*acc+b1) @ W2) ---
#define XS2_STRIDE 69
#define G2_SMEM (HID_CH*OUT_CH*4 + 128*XS2_STRIDE*4)   // 51712
__global__ void __launch_bounds__(128) gemm2_kernel(
    const float* __restrict__ b1, const float* __restrict__ W2)
{
    extern __shared__ float smem[];
    float* Wp = smem;                       // [64][64]
    float* xs = smem + HID_CH * OUT_CH;     // [128][69]
    int tid = threadIdx.x;
    int row0 = blockIdx.x * 128;

    for (int i = tid; i < (HID_CH * OUT_CH) / 4; i += 128)
        ((float4*)Wp)[i] = ((const float4*)W2)[i];

    for (int i = tid; i < 128 * 16; i += 128) {
        int r  = i >> 4;
        int k4 = (i & 15) * 4;
        int gr = row0 + r;
        float4 o = make_float4(0.f, 0.f, 0.f, 0.f);
        if (gr < N_NODES) {
            float dv = g_dinv[gr];
            float4 av = ((const float4*)g_acc)[(size_t)gr * 16 + (k4 >> 2)];
            float4 bv = __ldg(((const float4*)b1) + (k4 >> 2));
            o.x = fmaxf(fmaf(dv, av.x, bv.x), 0.f);
            o.y = fmaxf(fmaf(dv, av.y, bv.y), 0.f);
            o.z = fmaxf(fmaf(dv, av.z, bv.z), 0.f);
            o.w = fmaxf(fmaf(dv, av.w, bv.w), 0.f);
        }
        float* p = xs + r * XS2_STRIDE + k4;
        p[0] = o.x; p[1] = o.y; p[2] = o.z; p[3] = o.w;
    }
    __syncthreads();

    int cg = tid & 7;
    int rg = tid >> 3;
    const float* xrow = xs + rg * 8 * XS2_STRIDE;

    float acc[8][8];
    #pragma unroll
    for (int j = 0; j < 8; j++)
        #pragma unroll
        for (int c = 0; c < 8; c++) acc[j][c] = 0.f;

    #pragma unroll 4
    for (int k = 0; k < HID_CH; k++) {
        float4 wa = *(const float4*)&Wp[k * OUT_CH + cg * 8];
        float4 wb = *(const float4*)&Wp[k * OUT_CH + cg * 8 + 4];
        float xv[8];
        #pragma unroll
        for (int j = 0; j < 8; j++) xv[j] = xrow[j * XS2_STRIDE + k];
        #pragma unroll
        for (int j = 0; j < 8; j++) {
            acc[j][0] = fmaf(xv[j], wa.x, acc[j][0]);
            acc[j][1] = fmaf(xv[j], wa.y, acc[j][1]);
            acc[j][2] = fmaf(xv[j], wa.z, acc[j][2]);
            acc[j][3] = fmaf(xv[j], wa.w, acc[j][3]);
            acc[j][4] = fmaf(xv[j], wb.x, acc[j][4]);
            acc[j][5] = fmaf(xv[j], wb.y, acc[j][5]);
            acc[j][6] = fmaf(xv[j], wb.z, acc[j][6]);
            acc[j][7] = fmaf(xv[j], wb.w, acc[j][7]);
        }
    }

    #pragma unroll
    for (int j = 0; j < 8; j++) {
        int gr = row0 + rg * 8 + j;
        if (gr < N_NODES) {
            float dv = g_dinv[gr];
            float4 o0 = make_float4(acc[j][0]*dv, acc[j][1]*dv, acc[j][2]*dv, acc[j][3]*dv);
            float4 o1 = make_float4(acc[j][4]*dv, acc[j][5]*dv, acc[j][6]*dv, acc[j][7]*dv);
            ((float4*)g_h2)[(size_t)gr * 16 + cg * 2 + 0] = o0;
            ((float4*)g_h2)[(size_t)gr * 16 + cg * 2 + 1] = o1;
        }
    }
}

extern "C" void kernel_launch(void* const* d_in, const int* in_sizes, int n_in,
                              void* d_out, int out_size)
{
    // ---- identify inputs by element count ----
    const float* x  = nullptr;
    const void*  ei = nullptr;
    const float* W1 = nullptr;
    const float* b1 = nullptr;
    const float* W2 = nullptr;
    const float* b2 = nullptr;
    for (int i = 0; i < n_in; i++) {
        long long s = in_sizes[i];
        if      (s == (long long)N_NODES * IN_CH) x  = (const float*)d_in[i];
        else if (s == 2LL * N_EDGES)              ei = d_in[i];
        else if (s == (long long)IN_CH * HID_CH)  W1 = (const float*)d_in[i];
        else if (s == (long long)HID_CH * OUT_CH) W2 = (const float*)d_in[i];
        else if (s == HID_CH) { if (!b1) b1 = (const float*)d_in[i];
                                else     b2 = (const float*)d_in[i]; }
    }
    if (!x || !ei || !W1 || !b1 || !W2 || !b2) {
        x  = (const float*)d_in[0];
        ei = d_in[1];
        W1 = (const float*)d_in[2];
        b1 = (const float*)d_in[3];
        W2 = (const float*)d_in[4];
        b2 = (const float*)d_in[5];
    }
    float* outp = (float*)d_out;

    static cudaStream_t sB = nullptr;
    static cudaEvent_t  evA = nullptr, evB = nullptr;
    if (!sB) {
        cudaStreamCreateWithFlags(&sB, cudaStreamNonBlocking);
        cudaEventCreateWithFlags(&evA, cudaEventDisableTiming);
        cudaEventCreateWithFlags(&evB, cudaEventDisableTiming);
        cudaFuncSetAttribute(gemm1_kernel,
                             cudaFuncAttributeMaxDynamicSharedMemorySize, G1_SMEM);
        cudaFuncSetAttribute(gemm2_kernel,
                             cudaFuncAttributeMaxDynamicSharedMemorySize, G2_SMEM);
    }

    const int AGG_BLOCKS  = (N_NODES * 16) / 256;    // 6250
    const int GEMM_BLOCKS = (N_NODES + 127) / 128;   // 782

    // preprocessing head (main stream)
    probe_init_kernel<<<(N_NODES + 255) / 256, 256>>>(ei);
    convert_count_kernel<<<(N_EDGES / 2 + 255) / 256, 256>>>(ei);

    // fork: gemm1 (needs only g_deg + x/W1) runs concurrent with CSR build
    cudaEventRecord(evA, 0);
    cudaStreamWaitEvent(sB, evA, 0);
    gemm1_kernel<<<GEMM_BLOCKS, 128, G1_SMEM, sB>>>(x, W1);
    cudaEventRecord(evB, sB);

    // CSR build (main stream)
    scan1_kernel<<<SCAN_BLOCKS, 256>>>();
    scan2_kernel<<<1, 128>>>();
    scan3_kernel<<<(N_NODES + 255) / 256, 256>>>();
    scatter_kernel<<<(N_EDGES + 255) / 256, 256>>>();

    // join: agg1 needs both gemm1 (g_hs) and scatter (g_csr/g_start)
    cudaStreamWaitEvent(0, evB, 0);
    agg1_kernel<<<AGG_BLOCKS, 256>>>();

    // layer 2 (serial dependency chain)
    gemm2_kernel<<<GEMM_BLOCKS, 128, G2_SMEM>>>(b1, W2);
    agg2_kernel<<<AGG_BLOCKS, 256>>>(outp, b2);
}

// round 15
// speedup vs baseline: 1.0806x; 1.0057x over previous
#include <cuda_runtime.h>
#include <cuda_bf16.h>

#define N_NODES 100000
#define N_EDGES 1600000
#define IN_CH 128
#define HID_CH 64
#define OUT_CH 64

#define SCAN_CHUNK 1024
#define SCAN_BLOCKS ((N_NODES + SCAN_CHUNK - 1) / SCAN_CHUNK)   // 98

// ---------------- scratch (device globals; device-code access ONLY) ---------
__device__ int   g_idx64;
__device__ int   g_row[N_EDGES];
__device__ int   g_col[N_EDGES];
__device__ int   g_csr[N_EDGES];            // source indices grouped by dst
__device__ int   g_deg[N_NODES];            // 1 + in-degree (self-loop incl.)
__device__ int   g_start[N_NODES + 1];      // CSR offsets (edges only)
__device__ int   g_cur[N_NODES];            // scatter cursors
__device__ int   g_bsum[SCAN_BLOCKS];
__device__ float g_dinv[N_NODES];
__device__ float g_hs [N_NODES * HID_CH];   // dinv-scaled layer-1 msg source
__device__ float g_acc[N_NODES * HID_CH];   // layer-1 aggregation result
__device__ float g_h2 [N_NODES * HID_CH];   // layer-2 msg source

// ---------------- probe (block 0) + deg init (all blocks), one launch --------
__global__ void probe_init_kernel(const void* ei) {
    int i = blockIdx.x * blockDim.x + threadIdx.x;
    if (i < N_NODES) g_deg[i] = 1;   // self-loop
    if (blockIdx.x == 0) {
        __shared__ int ok;
        if (threadIdx.x == 0) ok = 1;
        __syncthreads();
        const long long* p = (const long long*)ei;
        for (int j = threadIdx.x; j < 1024; j += blockDim.x) {
            long long v = p[j];
            if (v < 0 || v >= N_NODES) ok = 0;
        }
        __syncthreads();
        if (threadIdx.x == 0) g_idx64 = ok;
    }
}

// col half only: convert + clamp + degree histogram (critical path to the fork)
__global__ void count_kernel(const void* ei) {
    int t = blockIdx.x * blockDim.x + threadIdx.x;
    int e = t * 2;
    if (e >= N_EDGES) return;
    long long c0, c1;
    if (g_idx64) {
        const longlong2* p = (const longlong2*)ei;
        longlong2 cc = p[(N_EDGES / 2) + t];
        c0 = cc.x; c1 = cc.y;
    } else {
        const int2* p = (const int2*)ei;
        int2 cc = p[(N_EDGES / 2) + t];
        c0 = cc.x; c1 = cc.y;
    }
    if (c0 < 0) c0 = 0; if (c0 >= N_NODES) c0 = N_NODES - 1;
    if (c1 < 0) c1 = 0; if (c1 >= N_NODES) c1 = N_NODES - 1;
    g_col[e]     = (int)c0;
    g_col[e + 1] = (int)c1;
    atomicAdd(&g_deg[(int)c0], 1);
    atomicAdd(&g_deg[(int)c1], 1);
}

// row half: convert + clamp (side stream; only scatter depends on it)
__global__ void row_convert_kernel(const void* ei) {
    int t = blockIdx.x * blockDim.x + threadIdx.x;
    int e = t * 2;
    if (e >= N_EDGES) return;
    long long r0, r1;
    if (g_idx64) {
        const longlong2* p = (const longlong2*)ei;
        longlong2 rr = p[t];
        r0 = rr.x; r1 = rr.y;
    } else {
        const int2* p = (const int2*)ei;
        int2 rr = p[t];
        r0 = rr.x; r1 = rr.y;
    }
    if (r0 < 0) r0 = 0; if (r0 >= N_NODES) r0 = N_NODES - 1;
    if (r1 < 0) r1 = 0; if (r1 >= N_NODES) r1 = N_NODES - 1;
    g_row[e]     = (int)r0;
    g_row[e + 1] = (int)r1;
}

// ---------------- CSR build: scan + scatter -----------------------------------
__global__ void __launch_bounds__(256) scan1_kernel() {
    __shared__ int warp_sums[8];
    int b   = blockIdx.x;
    int tid = threadIdx.x;
    int base = b * SCAN_CHUNK + tid * 4;

    int v0 = 0, v1 = 0, v2 = 0, v3 = 0;
    if (base + 0 < N_NODES) v0 = g_deg[base + 0] - 1;
    if (base + 1 < N_NODES) v1 = g_deg[base + 1] - 1;
    if (base + 2 < N_NODES) v2 = g_deg[base + 2] - 1;
    if (base + 3 < N_NODES) v3 = g_deg[base + 3] - 1;
    int tsum = v0 + v1 + v2 + v3;

    int lane = tid & 31, wid = tid >> 5;
    int s = tsum;
    #pragma unroll
    for (int off = 1; off < 32; off <<= 1) {
        int t = __shfl_up_sync(0xffffffffu, s, off);
        if (lane >= off) s += t;
    }
    if (lane == 31) warp_sums[wid] = s;
    __syncthreads();
    if (tid == 0) {
        int acc = 0;
        #pragma unroll
        for (int j = 0; j < 8; j++) { int t = warp_sums[j]; warp_sums[j] = acc; acc += t; }
        g_bsum[b] = acc;
    }
    __syncthreads();

    int excl = warp_sums[wid] + (s - tsum);
    if (base + 0 < N_NODES) g_start[base + 0] = excl; excl += v0;
    if (base + 1 < N_NODES) g_start[base + 1] = excl; excl += v1;
    if (base + 2 < N_NODES) g_start[base + 2] = excl; excl += v2;
    if (base + 3 < N_NODES) g_start[base + 3] = excl;
}

// parallel exclusive scan of the 98 block sums
__global__ void scan2_kernel() {
    __shared__ int ws[4];
    int tid = threadIdx.x;
    int v = (tid < SCAN_BLOCKS) ? g_bsum[tid] : 0;
    int lane = tid & 31, w = tid >> 5;
    int s = v;
    #pragma unroll
    for (int off = 1; off < 32; off <<= 1) {
        int t = __shfl_up_sync(0xffffffffu, s, off);
        if (lane >= off) s += t;
    }
    if (lane == 31) ws[w] = s;
    __syncthreads();
    int add = 0;
    #pragma unroll
    for (int j = 0; j < 4; j++) if (j < w) add += ws[j];
    s += add;
    if (tid < SCAN_BLOCKS) g_bsum[tid] = s - v;   // exclusive
}

// scan3 + dinv + cursor init fused
__global__ void scan3_kernel() {
    int i = blockIdx.x * blockDim.x + threadIdx.x;
    if (i < N_NODES) {
        int v = g_start[i] + g_bsum[i / SCAN_CHUNK];
        g_start[i] = v;
        g_cur[i]   = v;
        g_dinv[i]  = rsqrtf((float)g_deg[i]);
    }
    if (i == 0) g_start[N_NODES] = N_EDGES;
}

__global__ void scatter_kernel() {
    int e = blockIdx.x * blockDim.x + threadIdx.x;
    if (e >= N_EDGES) return;
    int c = g_col[e];
    int pos = atomicAdd(&g_cur[c], 1);
    g_csr[pos] = g_row[e];
}

// ---------------- layer-1 GEMM (8x8 register tile): hs = dinv * (x @ W1) -----
// Forked stream; depends only on g_deg (dinv inline).
#define XS1_STRIDE 133
#define G1_SMEM (IN_CH*HID_CH*4 + 128*XS1_STRIDE*4)   // 100864
__global__ void __launch_bounds__(128) gemm1_kernel(
    const float* __restrict__ x, const float* __restrict__ W1)
{
    extern __shared__ float smem[];
    float* Wp = smem;                       // [128][64]
    float* xs = smem + IN_CH * HID_CH;      // [128][133]
    int tid = threadIdx.x;
    int row0 = blockIdx.x * 128;

    for (int i = tid; i < (IN_CH * HID_CH) / 4; i += 128)
        ((float4*)Wp)[i] = ((const float4*)W1)[i];

    for (int i = tid; i < 128 * 32; i += 128) {
        int r  = i >> 5;
        int k4 = (i & 31) * 4;
        int gr = row0 + r;
        float4 v = make_float4(0.f, 0.f, 0.f, 0.f);
        if (gr < N_NODES)
            v = ((const float4*)(x + (size_t)gr * IN_CH))[k4 >> 2];
        float* p = xs + r * XS1_STRIDE + k4;
        p[0] = v.x; p[1] = v.y; p[2] = v.z; p[3] = v.w;
    }
    __syncthreads();

    int cg = tid & 7;
    int rg = tid >> 3;
    const float* xrow = xs + rg * 8 * XS1_STRIDE;

    float acc[8][8];
    #pragma unroll
    for (int j = 0; j < 8; j++)
        #pragma unroll
        for (int c = 0; c < 8; c++) acc[j][c] = 0.f;

    #pragma unroll 4
    for (int k = 0; k < IN_CH; k++) {
        float4 wa = *(const float4*)&Wp[k * HID_CH + cg * 8];
        float4 wb = *(const float4*)&Wp[k * HID_CH + cg * 8 + 4];
        float xv[8];
        #pragma unroll
        for (int j = 0; j < 8; j++) xv[j] = xrow[j * XS1_STRIDE + k];
        #pragma unroll
        for (int j = 0; j < 8; j++) {
            acc[j][0] = fmaf(xv[j], wa.x, acc[j][0]);
            acc[j][1] = fmaf(xv[j], wa.y, acc[j][1]);
            acc[j][2] = fmaf(xv[j], wa.z, acc[j][2]);
            acc[j][3] = fmaf(xv[j], wa.w, acc[j][3]);
            acc[j][4] = fmaf(xv[j], wb.x, acc[j][4]);
            acc[j][5] = fmaf(xv[j], wb.y, acc[j][5]);
            acc[j][6] = fmaf(xv[j], wb.z, acc[j][6]);
            acc[j][7] = fmaf(xv[j], wb.w, acc[j][7]);
        }
    }

    #pragma unroll
    for (int j = 0; j < 8; j++) {
        int gr = row0 + rg * 8 + j;
        if (gr < N_NODES) {
            float dv = rsqrtf((float)g_deg[gr]);
            float4 o0 = make_float4(acc[j][0]*dv, acc[j][1]*dv, acc[j][2]*dv, acc[j][3]*dv);
            float4 o1 = make_float4(acc[j][4]*dv, acc[j][5]*dv, acc[j][6]*dv, acc[j][7]*dv);
            ((float4*)g_hs)[(size_t)gr * 16 + cg * 2 + 0] = o0;
            ((float4*)g_hs)[(size_t)gr * 16 + cg * 2 + 1] = o1;
        }
    }
}

// ---------------- gather-side aggregation (atomic-free, unroll-4) ------------
__global__ void __launch_bounds__(256) agg1_kernel()
{
    int t = blockIdx.x * blockDim.x + threadIdx.x;
    int n = t >> 4;
    int q = t & 15;
    if (n >= N_NODES) return;
    const float4* s4 = (const float4*)g_hs;

    float4 a = s4[(size_t)n * 16 + q];       // self-loop term
    float sx = a.x, sy = a.y, sz = a.z, sw = a.w;

    int i   = g_start[n];
    int end = g_start[n + 1];
    for (; i + 3 < end; i += 4) {
        int e0 = g_csr[i],     e1 = g_csr[i + 1];
        int e2 = g_csr[i + 2], e3 = g_csr[i + 3];
        float4 v0 = s4[(size_t)e0 * 16 + q];
        float4 v1 = s4[(size_t)e1 * 16 + q];
        float4 v2 = s4[(size_t)e2 * 16 + q];
        float4 v3 = s4[(size_t)e3 * 16 + q];
        sx += v0.x + v1.x + v2.x + v3.x;
        sy += v0.y + v1.y + v2.y + v3.y;
        sz += v0.z + v1.z + v2.z + v3.z;
        sw += v0.w + v1.w + v2.w + v3.w;
    }
    for (; i < end; i++) {
        int e0 = g_csr[i];
        float4 v0 = s4[(size_t)e0 * 16 + q];
        sx += v0.x; sy += v0.y; sz += v0.z; sw += v0.w;
    }
    ((float4*)g_acc)[(size_t)n * 16 + q] = make_float4(sx, sy, sz, sw);
}

// layer-2 aggregation fused with final epilogue: out = dinv[n]*sum + b2
__global__ void __launch_bounds__(256) agg2_kernel(
    float* __restrict__ outp, const float* __restrict__ b2)
{
    int t = blockIdx.x * blockDim.x + threadIdx.x;
    int n = t >> 4;
    int q = t & 15;
    if (n >= N_NODES) return;
    const float4* s4 = (const float4*)g_h2;

    float4 a = s4[(size_t)n * 16 + q];
    float sx = a.x, sy = a.y, sz = a.z, sw = a.w;

    int i   = g_start[n];
    int end = g_start[n + 1];
    for (; i + 3 < end; i += 4) {
        int e0 = g_csr[i],     e1 = g_csr[i + 1];
        int e2 = g_csr[i + 2], e3 = g_csr[i + 3];
        float4 v0 = s4[(size_t)e0 * 16 + q];
        float4 v1 = s4[(size_t)e1 * 16 + q];
        float4 v2 = s4[(size_t)e2 * 16 + q];
        float4 v3 = s4[(size_t)e3 * 16 + q];
        sx += v0.x + v1.x + v2.x + v3.x;
        sy += v0.y + v1.y + v2.y + v3.y;
        sz += v0.z + v1.z + v2.z + v3.z;
        sw += v0.w + v1.w + v2.w + v3.w;
    }
    for (; i < end; i++) {
        int e0 = g_csr[i];
        float4 v0 = s4[(size_t)e0 * 16 + q];
        sx += v0.x; sy += v0.y; sz += v0.z; sw += v0.w;
    }
    float dv = g_dinv[n];
    float4 bb = ((const float4*)b2)[q];
    float4 o;
    o.x = fmaf(dv, sx, bb.x);
    o.y = fmaf(dv, sy, bb.y);
    o.z = fmaf(dv, sz, bb.z);
    o.w = fmaf(dv, sw, bb.w);
    ((float4*)outp)[(size_t)n * 16 + q] = o;
}

// ---------------- layer-2 GEMM (8x8): h2 = dinv * (relu(dinv*acc+b1) @ W2) ---
#define XS2_STRIDE 69
#define G2_SMEM (HID_CH*OUT_CH*4 + 128*XS2_STRIDE*4)   // 51712
__global__ void __launch_bounds__(128) gemm2_kernel(
    const float* __restrict__ b1, const float* __restrict__ W2)
{
    extern __shared__ float smem[];
    float* Wp = smem;                       // [64][64]
    float* xs = smem + HID_CH * OUT_CH;     // [128][69]
    int tid = threadIdx.x;
    int row0 = blockIdx.x * 128;

    for (int i = tid; i < (HID_CH * OUT_CH) / 4; i += 128)
        ((float4*)Wp)[i] = ((const float4*)W2)[i];

    for (int i = tid; i < 128 * 16; i += 128) {
        int r  = i >> 4;
        int k4 = (i & 15) * 4;
        int gr = row0 + r;
        float4 o = make_float4(0.f, 0.f, 0.f, 0.f);
        if (gr < N_NODES) {
            float dv = g_dinv[gr];
            float4 av = ((const float4*)g_acc)[(size_t)gr * 16 + (k4 >> 2)];
            float4 bv = __ldg(((const float4*)b1) + (k4 >> 2));
            o.x = fmaxf(fmaf(dv, av.x, bv.x), 0.f);
            o.y = fmaxf(fmaf(dv, av.y, bv.y), 0.f);
            o.z = fmaxf(fmaf(dv, av.z, bv.z), 0.f);
            o.w = fmaxf(fmaf(dv, av.w, bv.w), 0.f);
        }
        float* p = xs + r * XS2_STRIDE + k4;
        p[0] = o.x; p[1] = o.y; p[2] = o.z; p[3] = o.w;
    }
    __syncthreads();

    int cg = tid & 7;
    int rg = tid >> 3;
    const float* xrow = xs + rg * 8 * XS2_STRIDE;

    float acc[8][8];
    #pragma unroll
    for (int j = 0; j < 8; j++)
        #pragma unroll
        for (int c = 0; c < 8; c++) acc[j][c] = 0.f;

    #pragma unroll 4
    for (int k = 0; k < HID_CH; k++) {
        float4 wa = *(const float4*)&Wp[k * OUT_CH + cg * 8];
        float4 wb = *(const float4*)&Wp[k * OUT_CH + cg * 8 + 4];
        float xv[8];
        #pragma unroll
        for (int j = 0; j < 8; j++) xv[j] = xrow[j * XS2_STRIDE + k];
        #pragma unroll
        for (int j = 0; j < 8; j++) {
            acc[j][0] = fmaf(xv[j], wa.x, acc[j][0]);
            acc[j][1] = fmaf(xv[j], wa.y, acc[j][1]);
            acc[j][2] = fmaf(xv[j], wa.z, acc[j][2]);
            acc[j][3] = fmaf(xv[j], wa.w, acc[j][3]);
            acc[j][4] = fmaf(xv[j], wb.x, acc[j][4]);
            acc[j][5] = fmaf(xv[j], wb.y, acc[j][5]);
            acc[j][6] = fmaf(xv[j], wb.z, acc[j][6]);
            acc[j][7] = fmaf(xv[j], wb.w, acc[j][7]);
        }
    }

    #pragma unroll
    for (int j = 0; j < 8; j++) {
        int gr = row0 + rg * 8 + j;
        if (gr < N_NODES) {
            float dv = g_dinv[gr];
            float4 o0 = make_float4(acc[j][0]*dv, acc[j][1]*dv, acc[j][2]*dv, acc[j][3]*dv);
            float4 o1 = make_float4(acc[j][4]*dv, acc[j][5]*dv, acc[j][6]*dv, acc[j][7]*dv);
            ((float4*)g_h2)[(size_t)gr * 16 + cg * 2 + 0] = o0;
            ((float4*)g_h2)[(size_t)gr * 16 + cg * 2 + 1] = o1;
        }
    }
}

extern "C" void kernel_launch(void* const* d_in, const int* in_sizes, int n_in,
                              void* d_out, int out_size)
{
    // ---- identify inputs by element count ----
    const float* x  = nullptr;
    const void*  ei = nullptr;
    const float* W1 = nullptr;
    const float* b1 = nullptr;
    const float* W2 = nullptr;
    const float* b2 = nullptr;
    for (int i = 0; i < n_in; i++) {
        long long s = in_sizes[i];
        if      (s == (long long)N_NODES * IN_CH) x  = (const float*)d_in[i];
        else if (s == 2LL * N_EDGES)              ei = d_in[i];
        else if (s == (long long)IN_CH * HID_CH)  W1 = (const float*)d_in[i];
        else if (s == (long long)HID_CH * OUT_CH) W2 = (const float*)d_in[i];
        else if (s == HID_CH) { if (!b1) b1 = (const float*)d_in[i];
                                else     b2 = (const float*)d_in[i]; }
    }
    if (!x || !ei || !W1 || !b1 || !W2 || !b2) {
        x  = (const float*)d_in[0];
        ei = d_in[1];
        W1 = (const float*)d_in[2];
        b1 = (const float*)d_in[3];
        W2 = (const float*)d_in[4];
        b2 = (const float*)d_in[5];
    }
    float* outp = (float*)d_out;

    static cudaStream_t sB = nullptr, sC = nullptr;
    static cudaEvent_t  evP = nullptr, evA = nullptr, evB = nullptr, evR = nullptr;
    if (!sB) {
        cudaStreamCreateWithFlags(&sB, cudaStreamNonBlocking);
        cudaStreamCreateWithFlags(&sC, cudaStreamNonBlocking);
        cudaEventCreateWithFlags(&evP, cudaEventDisableTiming);
        cudaEventCreateWithFlags(&evA, cudaEventDisableTiming);
        cudaEventCreateWithFlags(&evB, cudaEventDisableTiming);
        cudaEventCreateWithFlags(&evR, cudaEventDisableTiming);
        cudaFuncSetAttribute(gemm1_kernel,
                             cudaFuncAttributeMaxDynamicSharedMemorySize, G1_SMEM);
        cudaFuncSetAttribute(gemm2_kernel,
                             cudaFuncAttributeMaxDynamicSharedMemorySize, G2_SMEM);
    }

    const int AGG_BLOCKS  = (N_NODES * 16) / 256;    // 6250
    const int GEMM_BLOCKS = (N_NODES + 127) / 128;   // 782
    const int CVT_BLOCKS  = (N_EDGES / 2 + 255) / 256;

    // head: probe+init, then col-count (critical), row-convert forked off
    probe_init_kernel<<<(N_NODES + 255) / 256, 256>>>(ei);
    cudaEventRecord(evP, 0);
    cudaStreamWaitEvent(sC, evP, 0);
    row_convert_kernel<<<CVT_BLOCKS, 256, 0, sC>>>(ei);
    cudaEventRecord(evR, sC);

    count_kernel<<<CVT_BLOCKS, 256>>>(ei);

    // fork: gemm1 (needs only g_deg + x/W1) runs concurrent with CSR build
    cudaEventRecord(evA, 0);
    cudaStreamWaitEvent(sB, evA, 0);
    gemm1_kernel<<<GEMM_BLOCKS, 128, G1_SMEM, sB>>>(x, W1);
    cudaEventRecord(evB, sB);

    // CSR build (main stream)
    scan1_kernel<<<SCAN_BLOCKS, 256>>>();
    scan2_kernel<<<1, 128>>>();
    scan3_kernel<<<(N_NODES + 255) / 256, 256>>>();
    cudaStreamWaitEvent(0, evR, 0);   // scatter needs g_row
    scatter_kernel<<<(N_EDGES + 255) / 256, 256>>>();

    // join: agg1 needs both gemm1 (g_hs) and scatter (g_csr/g_start)
    cudaStreamWaitEvent(0, evB, 0);
    agg1_kernel<<<AGG_BLOCKS, 256>>>();

    // layer 2 (serial dependency chain)
    gemm2_kernel<<<GEMM_BLOCKS, 128, G2_SMEM>>>(b1, W2);
    agg2_kernel<<<AGG_BLOCKS, 256>>>(outp, b2);
}